// round 10
// baseline (speedup 1.0000x reference)
#include <cuda_runtime.h>

#define MGRAPHS 8192
#define NODES   64
#define DH      128
#define DX      128

// 4 MB scratch for HA = h @ a  (device global: allocation-free, allowed)
__device__ float g_HA[MGRAPHS * DX];

// ---------- packed f32x2 helpers (sm_100+ FFMA2 path) ----------
static __device__ __forceinline__ unsigned long long pack2_dup(float v) {
    unsigned long long r;
    asm("mov.b64 %0, {%1, %1};" : "=l"(r) : "f"(v));
    return r;
}
static __device__ __forceinline__ unsigned long long fma2(unsigned long long a,
                                                          unsigned long long b,
                                                          unsigned long long c) {
    unsigned long long d;
    asm("fma.rn.f32x2 %0, %1, %2, %3;" : "=l"(d) : "l"(a), "l"(b), "l"(c));
    return d;
}
static __device__ __forceinline__ float2 unpack2(unsigned long long v) {
    float lo, hi;
    asm("mov.b64 {%0, %1}, %2;" : "=f"(lo), "=f"(hi) : "l"(v));
    float2 f; f.x = lo; f.y = hi; return f;
}

// ============================================================================
// Kernel 1: HA[g][d] = sum_k h[g][k] * a[k][d]
// SINGLE WAVE: 128 blocks x 512 threads; each block computes 64 graph rows.
// Full a (64 KB) staged once in smem with a lo/hi permutation so the per-k
// LDS.128 reads are bank-conflict-free:
//   float4 column c = 2g+u  ->  col4 = u ? (16+g) : g
// Lane group g (= t&15) then reads floats [g*4..g*4+3] and [64+g*4..+3].
// h tile (64x128, stride 132) hoisted into registers in k-chunks of 16.
// Thread t computes 2 graphs x 8 dims, accumulated as 8 f32x2 pairs.
// ============================================================================
__global__ void __launch_bounds__(512) ha_kernel(const float* __restrict__ h,
                                                 const float* __restrict__ a) {
    // signal PDL dependents as early as possible (attn's x loads don't need us)
    asm volatile("griddepcontrol.launch_dependents;");

    __shared__ float a_s[DH * DX];   // 64 KB, permuted rows
    __shared__ float h_s[64 * 132];  // 33 KB (row stride 132 floats, conflict-free)

    const int t     = threadIdx.x;
    const int gbase = blockIdx.x * 64;

    // stage a: 4096 float4, permuted lo/hi halves
    const float4* a4  = (const float4*)a;
    float4*       as4 = (float4*)a_s;
#pragma unroll
    for (int q = 0; q < 8; q++) {
        int idx = t + 512 * q;
        int k   = idx >> 5;        // row
        int c   = idx & 31;        // float4 column
        int gg  = c >> 1, u = c & 1;
        int col4 = u ? (16 + gg) : gg;
        as4[k * 32 + col4] = a4[idx];
    }
    // stage h: 64 rows x 128 floats = 2048 float4
#pragma unroll
    for (int q = 0; q < 4; q++) {
        int idx = t + 512 * q;
        int row = idx >> 5, c4 = idx & 31;
        float4 hv = *(const float4*)(h + (size_t)(gbase + row) * DH + c4 * 4);
        *(float4*)(&h_s[row * 132 + c4 * 4]) = hv;
    }
    __syncthreads();

    const int g    = t & 15;        // dim group: dims g*8 .. g*8+7
    const int grow = (t >> 4) * 2;  // local graphs grow, grow+1 (0..63)

    unsigned long long acc[2][4];
#pragma unroll
    for (int j = 0; j < 2; j++)
#pragma unroll
        for (int p = 0; p < 4; p++) acc[j][p] = 0ULL;

#pragma unroll 1
    for (int kc = 0; kc < 8; kc++) {   // k chunks of 16
        float hreg[2][16];
#pragma unroll
        for (int j = 0; j < 2; j++)
#pragma unroll
            for (int q = 0; q < 4; q++)
                *(float4*)&hreg[j][q * 4] =
                    *(const float4*)&h_s[(grow + j) * 132 + kc * 16 + q * 4];

#pragma unroll
        for (int kk = 0; kk < 16; kk++) {
            const float* base = a_s + (kc * 16 + kk) * DX;
            ulonglong2 A0 = *(const ulonglong2*)(base + g * 4);        // dims g*8..+3
            ulonglong2 A1 = *(const ulonglong2*)(base + 64 + g * 4);   // dims g*8+4..+7
#pragma unroll
            for (int j = 0; j < 2; j++) {
                unsigned long long hp = pack2_dup(hreg[j][kk]);
                acc[j][0] = fma2(hp, A0.x, acc[j][0]);
                acc[j][1] = fma2(hp, A0.y, acc[j][1]);
                acc[j][2] = fma2(hp, A1.x, acc[j][2]);
                acc[j][3] = fma2(hp, A1.y, acc[j][3]);
            }
        }
    }

#pragma unroll
    for (int j = 0; j < 2; j++) {
        float* dst = g_HA + (size_t)(gbase + grow + j) * DX + g * 8;
        float2 v0 = unpack2(acc[j][0]), v1 = unpack2(acc[j][1]);
        float2 v2 = unpack2(acc[j][2]), v3 = unpack2(acc[j][3]);
        *(float4*)(dst)     = make_float4(v0.x, v0.y, v1.x, v1.y);
        *(float4*)(dst + 4) = make_float4(v2.x, v2.y, v3.x, v3.y);
    }
}

// ============================================================================
// Kernel 2: per-graph segment softmax attention, single pass over x.
// One CTA (1024 threads, 2 CTAs/SM -> 64 warps = 100% occ) per graph.
// Thread t keeps 2 float4s of x in registers:
//   float4 index j = t + 1024k  ->  node = w + 32k (w = warp),  dims = 4l.
// x loads are issued BEFORE griddepcontrol.wait so they overlap ha_kernel
// under PDL; g_HA is read only after the wait.
// ============================================================================
__global__ void __launch_bounds__(1024, 2) attn_kernel(const float* __restrict__ x,
                                                       float* __restrict__ out) {
    __shared__ float4 red[32][32];   // 16 KB
    __shared__ float4 red2[8][32];   // 4 KB
    __shared__ float4 zwv[8];        // 32 warp z-partials

    const int g = blockIdx.x;
    const int t = threadIdx.x;
    const int w = t >> 5, l = t & 31;

    // one contiguous 32 KB block per CTA; 2 front-batched LDG.128 per thread
    const float4* x4 = (const float4*)x + (size_t)g * (NODES * DX / 4);
    float4 xv[2];
    xv[0] = x4[t];
    xv[1] = x4[t + 1024];

    // PDL: wait for ha_kernel's g_HA writes (no-op if launched without PDL)
    asm volatile("griddepcontrol.wait;" ::: "memory");

    const float4 hav = ((const float4*)g_HA)[g * (DX / 4) + l];

    float att[2];
    float zsum = 0.0f;
#pragma unroll
    for (int k = 0; k < 2; k++) {
        float p = xv[k].x * hav.x + xv[k].y * hav.y + xv[k].z * hav.z + xv[k].w * hav.w;
#pragma unroll
        for (int o = 16; o; o >>= 1) p += __shfl_xor_sync(0xffffffffu, p, o);
        float ex = __expf(p);   // unstabilized, faithful to reference
        att[k] = ex;
        zsum  += ex;
    }
    if (l == 0) ((float*)zwv)[w] = zsum;   // lane-uniform after butterfly
    __syncthreads();

    float z = 0.0f;
#pragma unroll
    for (int j = 0; j < 8; j++) {          // broadcast LDS.128, no conflicts
        float4 zp = zwv[j];
        z += (zp.x + zp.y) + (zp.z + zp.w);
    }
    float inv = 1.0f / z;

    float4 o4;
    {
        float a0 = att[0] * inv, a1 = att[1] * inv;
        o4.x = a0 * xv[0].x + a1 * xv[1].x;
        o4.y = a0 * xv[0].y + a1 * xv[1].y;
        o4.z = a0 * xv[0].z + a1 * xv[1].z;
        o4.w = a0 * xv[0].w + a1 * xv[1].w;
    }
    red[w][l] = o4;
    __syncthreads();

    // stage 1: 256 threads, each sums 4 of the 32 warp partials for its column
    if (t < 256) {
        int col = t & 31, part = t >> 5;
        float4 s = red[part * 4 + 0][col];
#pragma unroll
        for (int j = 1; j < 4; j++) {
            float4 r = red[part * 4 + j][col];
            s.x += r.x; s.y += r.y; s.z += r.z; s.w += r.w;
        }
        red2[part][col] = s;
    }
    __syncthreads();

    // stage 2: warp 0 sums the 8 partials and writes out
    if (t < 32) {
        float4 s = red2[0][t];
#pragma unroll
        for (int j = 1; j < 8; j++) {
            float4 r = red2[j][t];
            s.x += r.x; s.y += r.y; s.z += r.z; s.w += r.w;
        }
        ((float4*)out)[g * (DX / 4) + t] = s;
    }
}

// ============================================================================
// inputs (metadata order): h (8192x128 f32), x (524288x128 f32),
//                          a (128x128 f32), batch_num_nodes (8192 i32, all 64)
// output: out (8192x128 f32)
// ============================================================================
extern "C" void kernel_launch(void* const* d_in, const int* in_sizes, int n_in,
                              void* d_out, int out_size) {
    const float* h = (const float*)d_in[0];
    const float* x = (const float*)d_in[1];
    const float* a = (const float*)d_in[2];
    float* out = (float*)d_out;
    (void)in_sizes; (void)n_in; (void)out_size;

    ha_kernel<<<MGRAPHS / 64, 512>>>(h, a);

    // attn with programmatic dependent launch (overlaps x loads with ha)
    cudaLaunchConfig_t cfg = {};
    cfg.gridDim  = dim3(MGRAPHS, 1, 1);
    cfg.blockDim = dim3(1024, 1, 1);
    cfg.dynamicSmemBytes = 0;
    cfg.stream = 0;
    cudaLaunchAttribute attr[1];
    attr[0].id = cudaLaunchAttributeProgrammaticStreamSerialization;
    attr[0].val.programmaticStreamSerializationAllowed = 1;
    cfg.attrs = attr;
    cfg.numAttrs = 1;
    cudaError_t e = cudaLaunchKernelEx(&cfg, attn_kernel, x, out);
    if (e != cudaSuccess || cudaGetLastError() != cudaSuccess) {
        attn_kernel<<<MGRAPHS, 1024>>>(x, out);  // plain serialized fallback
    }
}

// round 12
// speedup vs baseline: 1.2661x; 1.2661x over previous
#include <cuda_runtime.h>
#include <cstdint>

#define MGRAPHS 8192
#define NODES   64
#define DH      128
#define DX      128

#define ATTN_CTAS 444              // 148 SMs x 3 CTAs: exactly one wave
#define GRAPH_BYTES (NODES * DX * 4)   // 32768

// dynamic smem layout (bytes)
#define BUF0_OFF 0
#define BUF1_OFF 32768
#define RED_OFF  65536             // 16 warps x 32 lanes x float4 = 8192 B
#define ZWV_OFF  73728             // 16 floats
#define MBAR_OFF 73792             // 2 x u64
#define SMEM_BYTES 73856

// 4 MB scratch for HA = h @ a  (device global: allocation-free, allowed)
__device__ float g_HA[MGRAPHS * DX];

// ---------- packed f32x2 helpers (sm_100+ FFMA2 path) ----------
static __device__ __forceinline__ unsigned long long pack2_dup(float v) {
    unsigned long long r;
    asm("mov.b64 %0, {%1, %1};" : "=l"(r) : "f"(v));
    return r;
}
static __device__ __forceinline__ unsigned long long fma2(unsigned long long a,
                                                          unsigned long long b,
                                                          unsigned long long c) {
    unsigned long long d;
    asm("fma.rn.f32x2 %0, %1, %2, %3;" : "=l"(d) : "l"(a), "l"(b), "l"(c));
    return d;
}
static __device__ __forceinline__ float2 unpack2(unsigned long long v) {
    float lo, hi;
    asm("mov.b64 {%0, %1}, %2;" : "=f"(lo), "=f"(hi) : "l"(v));
    float2 f; f.x = lo; f.y = hi; return f;
}

static __device__ __forceinline__ uint32_t smem_u32(const void* p) {
    uint32_t a;
    asm("{ .reg .u64 t; cvta.to.shared.u64 t, %1; cvt.u32.u64 %0, t; }"
        : "=r"(a) : "l"(p));
    return a;
}
static __device__ __forceinline__ void mbar_init(uint32_t mbar, uint32_t cnt) {
    asm volatile("mbarrier.init.shared.b64 [%0], %1;" :: "r"(mbar), "r"(cnt) : "memory");
}
static __device__ __forceinline__ void mbar_wait(uint32_t mbar, uint32_t parity) {
    asm volatile(
        "{\n\t.reg .pred P;\n"
        "WL%=:\n\t"
        "mbarrier.try_wait.parity.acquire.cta.shared::cta.b64 P, [%0], %1, 0x989680;\n\t"
        "@P bra WD%=;\n\t"
        "bra WL%=;\n"
        "WD%=:\n\t}"
        :: "r"(mbar), "r"(parity) : "memory");
}
static __device__ __forceinline__ void bulk_load(uint32_t dst_smem, const void* src,
                                                 uint32_t bytes, uint32_t mbar) {
    asm volatile("mbarrier.arrive.expect_tx.shared.b64 _, [%0], %1;"
                 :: "r"(mbar), "r"(bytes) : "memory");
    asm volatile(
        "cp.async.bulk.shared::cluster.global.mbarrier::complete_tx::bytes "
        "[%0], [%1], %2, [%3];"
        :: "r"(dst_smem), "l"(src), "r"(bytes), "r"(mbar) : "memory");
}

// ============================================================================
// Kernel 1: HA[g][d] = sum_k h[g][k] * a[k][d]
// SINGLE WAVE: 128 blocks x 512 threads; each block computes 64 graph rows.
// Full a (64 KB) staged once in smem, lo/hi-permuted for conflict-free LDS.128.
// ============================================================================
__global__ void __launch_bounds__(512) ha_kernel(const float* __restrict__ h,
                                                 const float* __restrict__ a) {
    asm volatile("griddepcontrol.launch_dependents;");

    __shared__ float a_s[DH * DX];   // 64 KB, permuted rows
    __shared__ float h_s[64 * 132];  // 33 KB

    const int t     = threadIdx.x;
    const int gbase = blockIdx.x * 64;

    const float4* a4  = (const float4*)a;
    float4*       as4 = (float4*)a_s;
#pragma unroll
    for (int q = 0; q < 8; q++) {
        int idx = t + 512 * q;
        int k   = idx >> 5;
        int c   = idx & 31;
        int gg  = c >> 1, u = c & 1;
        int col4 = u ? (16 + gg) : gg;
        as4[k * 32 + col4] = a4[idx];
    }
#pragma unroll
    for (int q = 0; q < 4; q++) {
        int idx = t + 512 * q;
        int row = idx >> 5, c4 = idx & 31;
        float4 hv = *(const float4*)(h + (size_t)(gbase + row) * DH + c4 * 4);
        *(float4*)(&h_s[row * 132 + c4 * 4]) = hv;
    }
    __syncthreads();

    const int g    = t & 15;
    const int grow = (t >> 4) * 2;

    unsigned long long acc[2][4];
#pragma unroll
    for (int j = 0; j < 2; j++)
#pragma unroll
        for (int p = 0; p < 4; p++) acc[j][p] = 0ULL;

#pragma unroll 1
    for (int kc = 0; kc < 8; kc++) {
        float hreg[2][16];
#pragma unroll
        for (int j = 0; j < 2; j++)
#pragma unroll
            for (int q = 0; q < 4; q++)
                *(float4*)&hreg[j][q * 4] =
                    *(const float4*)&h_s[(grow + j) * 132 + kc * 16 + q * 4];

#pragma unroll
        for (int kk = 0; kk < 16; kk++) {
            const float* base = a_s + (kc * 16 + kk) * DX;
            ulonglong2 A0 = *(const ulonglong2*)(base + g * 4);
            ulonglong2 A1 = *(const ulonglong2*)(base + 64 + g * 4);
#pragma unroll
            for (int j = 0; j < 2; j++) {
                unsigned long long hp = pack2_dup(hreg[j][kk]);
                acc[j][0] = fma2(hp, A0.x, acc[j][0]);
                acc[j][1] = fma2(hp, A0.y, acc[j][1]);
                acc[j][2] = fma2(hp, A1.x, acc[j][2]);
                acc[j][3] = fma2(hp, A1.y, acc[j][3]);
            }
        }
    }

#pragma unroll
    for (int j = 0; j < 2; j++) {
        float* dst = g_HA + (size_t)(gbase + grow + j) * DX + g * 8;
        float2 v0 = unpack2(acc[j][0]), v1 = unpack2(acc[j][1]);
        float2 v2 = unpack2(acc[j][2]), v3 = unpack2(acc[j][3]);
        *(float4*)(dst)     = make_float4(v0.x, v0.y, v1.x, v1.y);
        *(float4*)(dst + 4) = make_float4(v2.x, v2.y, v3.x, v3.y);
    }
}

// ============================================================================
// Kernel 2: persistent segment-softmax attention.
// 444 CTAs x 512 threads, 3 CTAs/SM (48 warps). Each CTA streams 18-19
// consecutive graphs through 2 x 32 KB smem buffers filled by cp.async.bulk
// + mbarrier; the next graph's copy is re-issued immediately after the
// current buffer is drained into registers, so a bulk load is in flight
// during all compute/reduce phases. Thread mapping per graph (as R8):
//   float4 j = t + 512k (k<4) -> node = w + 16k, dims = 4l.
// ============================================================================
__global__ void __launch_bounds__(512, 3) attn_kernel(const float* __restrict__ x,
                                                      float* __restrict__ out) {
    extern __shared__ char smem[];
    const int t = threadIdx.x;
    const int w = t >> 5, l = t & 31;
    const int bid = blockIdx.x;

    // graphs [start, start+cnt): first 200 CTAs take 19, rest 18  (200*19+244*18=8192)
    const int start = bid * 18 + (bid < 200 ? bid : 200);
    const int cnt   = 18 + (bid < 200 ? 1 : 0);

    const uint32_t sb  = smem_u32(smem);
    const uint32_t mb0 = sb + MBAR_OFF;
    const uint32_t mb1 = sb + MBAR_OFF + 8;
    float4* red = (float4*)(smem + RED_OFF);    // [16][32]
    float4* zwv = (float4*)(smem + ZWV_OFF);    // 16 floats

    if (t == 0) {
        mbar_init(mb0, 1);
        mbar_init(mb1, 1);
        asm volatile("fence.proxy.async.shared::cta;" ::: "memory");
    }
    __syncthreads();

    // prologue: fill both buffers (x loads independent of ha_kernel)
    if (t == 0) {
        bulk_load(sb + BUF0_OFF, (const char*)x + (size_t)start * GRAPH_BYTES,
                  GRAPH_BYTES, mb0);
        if (cnt > 1)
            bulk_load(sb + BUF1_OFF, (const char*)x + (size_t)(start + 1) * GRAPH_BYTES,
                      GRAPH_BYTES, mb1);
    }

    // PDL: g_HA must be ready before the first read below
    asm volatile("griddepcontrol.wait;" ::: "memory");

    for (int i = 0; i < cnt; i++) {
        const int g = start + i;
        const int p = i & 1;

        // prefetch per-graph query before the barrier wait (hides LDG latency)
        const float4 hav = __ldg((const float4*)g_HA + g * (DX / 4) + l);

        mbar_wait(p ? mb1 : mb0, (i >> 1) & 1);

        // drain buffer into registers (conflict-free LDS.128)
        const float4* bp = (const float4*)(smem + (p ? BUF1_OFF : BUF0_OFF));
        float4 xv[4];
#pragma unroll
        for (int k = 0; k < 4; k++) xv[k] = bp[t + 512 * k];
        __syncthreads();   // B1: buffer p fully drained CTA-wide

        // immediately refill buffer p with graph i+2 (overlaps all compute below)
        if (t == 0 && i + 2 < cnt)
            bulk_load(sb + (p ? BUF1_OFF : BUF0_OFF),
                      (const char*)x + (size_t)(g + 2) * GRAPH_BYTES,
                      GRAPH_BYTES, p ? mb1 : mb0);

        // logits + unstabilized exp
        float att[4];
        float zsum = 0.0f;
#pragma unroll
        for (int k = 0; k < 4; k++) {
            float e = xv[k].x * hav.x + xv[k].y * hav.y + xv[k].z * hav.z + xv[k].w * hav.w;
#pragma unroll
            for (int o = 16; o; o >>= 1) e += __shfl_xor_sync(0xffffffffu, e, o);
            float ex = __expf(e);
            att[k] = ex;
            zsum  += ex;
        }
        if (l == 0) ((float*)zwv)[w] = zsum;   // lane-uniform after butterfly
        __syncthreads();   // B2

        float4 z0 = zwv[0], z1 = zwv[1], z2 = zwv[2], z3 = zwv[3];
        float z = (z0.x + z0.y + z0.z + z0.w) + (z1.x + z1.y + z1.z + z1.w) +
                  (z2.x + z2.y + z2.z + z2.w) + (z3.x + z3.y + z3.z + z3.w);
        float inv = 1.0f / z;

        float4 o4 = make_float4(0.f, 0.f, 0.f, 0.f);
#pragma unroll
        for (int k = 0; k < 4; k++) {
            float aw = att[k] * inv;
            o4.x += aw * xv[k].x;
            o4.y += aw * xv[k].y;
            o4.z += aw * xv[k].z;
            o4.w += aw * xv[k].w;
        }
        red[w * 32 + l] = o4;
        __syncthreads();   // B3

        if (t < 32) {
            float4 s = red[t];
#pragma unroll
            for (int j = 1; j < 16; j++) {
                float4 r = red[j * 32 + t];
                s.x += r.x; s.y += r.y; s.z += r.z; s.w += r.w;
            }
            ((float4*)out)[g * (DX / 4) + t] = s;
        }
        // no trailing barrier needed: next iteration's B1 orders red/zwv reuse
        // after warp0's reads above.
    }
}

// ============================================================================
// inputs (metadata order): h (8192x128 f32), x (524288x128 f32),
//                          a (128x128 f32), batch_num_nodes (8192 i32, all 64)
// output: out (8192x128 f32)
// ============================================================================
extern "C" void kernel_launch(void* const* d_in, const int* in_sizes, int n_in,
                              void* d_out, int out_size) {
    const float* h = (const float*)d_in[0];
    const float* x = (const float*)d_in[1];
    const float* a = (const float*)d_in[2];
    float* out = (float*)d_out;
    (void)in_sizes; (void)n_in; (void)out_size;

    cudaFuncSetAttribute(attn_kernel, cudaFuncAttributeMaxDynamicSharedMemorySize,
                         SMEM_BYTES);

    ha_kernel<<<MGRAPHS / 64, 512>>>(h, a);

    // attn with programmatic dependent launch (overlaps x loads with ha)
    cudaLaunchConfig_t cfg = {};
    cfg.gridDim  = dim3(ATTN_CTAS, 1, 1);
    cfg.blockDim = dim3(512, 1, 1);
    cfg.dynamicSmemBytes = SMEM_BYTES;
    cfg.stream = 0;
    cudaLaunchAttribute attr[1];
    attr[0].id = cudaLaunchAttributeProgrammaticStreamSerialization;
    attr[0].val.programmaticStreamSerializationAllowed = 1;
    cfg.attrs = attr;
    cfg.numAttrs = 1;
    cudaError_t e = cudaLaunchKernelEx(&cfg, attn_kernel, x, out);
    if (e != cudaSuccess || cudaGetLastError() != cudaSuccess) {
        attn_kernel<<<ATTN_CTAS, 512, SMEM_BYTES>>>(x, out);  // serialized fallback
    }
}

// round 14
// speedup vs baseline: 1.2922x; 1.0206x over previous
#include <cuda_runtime.h>
#include <cstdint>

#define MGRAPHS 8192
#define NODES   64
#define DH      128
#define DX      128

#define ATTN_CTAS 444              // 148 SMs x 3 CTAs: exactly one wave
#define GRAPH_BYTES (NODES * DX * 4)   // 32768

// dynamic smem layout (bytes)
#define BUF0_OFF 0
#define BUF1_OFF 32768
#define RED_OFF  65536             // 16 rows x 34 float4 (padded stride) = 8704 B
#define ZWV_OFF  74240             // 16 floats
#define MBAR_OFF 74304             // 2 x u64
#define SMEM_BYTES 74368           // x3 CTAs = 223104 <= 228KB

// 4 MB scratch for HA = h @ a  (device global: allocation-free, allowed)
__device__ float g_HA[MGRAPHS * DX];

// ---------- packed f32x2 helpers (sm_100+ FFMA2 path) ----------
static __device__ __forceinline__ unsigned long long pack2_dup(float v) {
    unsigned long long r;
    asm("mov.b64 %0, {%1, %1};" : "=l"(r) : "f"(v));
    return r;
}
static __device__ __forceinline__ unsigned long long fma2(unsigned long long a,
                                                          unsigned long long b,
                                                          unsigned long long c) {
    unsigned long long d;
    asm("fma.rn.f32x2 %0, %1, %2, %3;" : "=l"(d) : "l"(a), "l"(b), "l"(c));
    return d;
}
static __device__ __forceinline__ float2 unpack2(unsigned long long v) {
    float lo, hi;
    asm("mov.b64 {%0, %1}, %2;" : "=f"(lo), "=f"(hi) : "l"(v));
    float2 f; f.x = lo; f.y = hi; return f;
}

static __device__ __forceinline__ uint32_t smem_u32(const void* p) {
    uint32_t a;
    asm("{ .reg .u64 t; cvta.to.shared.u64 t, %1; cvt.u32.u64 %0, t; }"
        : "=r"(a) : "l"(p));
    return a;
}
static __device__ __forceinline__ void mbar_init(uint32_t mbar, uint32_t cnt) {
    asm volatile("mbarrier.init.shared.b64 [%0], %1;" :: "r"(mbar), "r"(cnt) : "memory");
}
static __device__ __forceinline__ void mbar_wait(uint32_t mbar, uint32_t parity) {
    asm volatile(
        "{\n\t.reg .pred P;\n"
        "WL%=:\n\t"
        "mbarrier.try_wait.parity.acquire.cta.shared::cta.b64 P, [%0], %1, 0x989680;\n\t"
        "@P bra WD%=;\n\t"
        "bra WL%=;\n"
        "WD%=:\n\t}"
        :: "r"(mbar), "r"(parity) : "memory");
}
static __device__ __forceinline__ void bulk_load(uint32_t dst_smem, const void* src,
                                                 uint32_t bytes, uint32_t mbar) {
    asm volatile("mbarrier.arrive.expect_tx.shared.b64 _, [%0], %1;"
                 :: "r"(mbar), "r"(bytes) : "memory");
    asm volatile(
        "cp.async.bulk.shared::cluster.global.mbarrier::complete_tx::bytes "
        "[%0], [%1], %2, [%3];"
        :: "r"(dst_smem), "l"(src), "r"(bytes), "r"(mbar) : "memory");
}

// ============================================================================
// Kernel 1: HA[g][d] = sum_k h[g][k] * a[k][d]
// SINGLE WAVE: 128 blocks x 512 threads; each block computes 64 graph rows.
// Full a (64 KB) staged once in smem, lo/hi-permuted for conflict-free LDS.128.
// (unchanged — proven; overlap handled by PDL)
// ============================================================================
__global__ void __launch_bounds__(512) ha_kernel(const float* __restrict__ h,
                                                 const float* __restrict__ a) {
    asm volatile("griddepcontrol.launch_dependents;");

    __shared__ float a_s[DH * DX];   // 64 KB, permuted rows
    __shared__ float h_s[64 * 132];  // 33 KB

    const int t     = threadIdx.x;
    const int gbase = blockIdx.x * 64;

    const float4* a4  = (const float4*)a;
    float4*       as4 = (float4*)a_s;
#pragma unroll
    for (int q = 0; q < 8; q++) {
        int idx = t + 512 * q;
        int k   = idx >> 5;
        int c   = idx & 31;
        int gg  = c >> 1, u = c & 1;
        int col4 = u ? (16 + gg) : gg;
        as4[k * 32 + col4] = a4[idx];
    }
#pragma unroll
    for (int q = 0; q < 4; q++) {
        int idx = t + 512 * q;
        int row = idx >> 5, c4 = idx & 31;
        float4 hv = *(const float4*)(h + (size_t)(gbase + row) * DH + c4 * 4);
        *(float4*)(&h_s[row * 132 + c4 * 4]) = hv;
    }
    __syncthreads();

    const int g    = t & 15;
    const int grow = (t >> 4) * 2;

    unsigned long long acc[2][4];
#pragma unroll
    for (int j = 0; j < 2; j++)
#pragma unroll
        for (int p = 0; p < 4; p++) acc[j][p] = 0ULL;

#pragma unroll 1
    for (int kc = 0; kc < 8; kc++) {
        float hreg[2][16];
#pragma unroll
        for (int j = 0; j < 2; j++)
#pragma unroll
            for (int q = 0; q < 4; q++)
                *(float4*)&hreg[j][q * 4] =
                    *(const float4*)&h_s[(grow + j) * 132 + kc * 16 + q * 4];

#pragma unroll
        for (int kk = 0; kk < 16; kk++) {
            const float* base = a_s + (kc * 16 + kk) * DX;
            ulonglong2 A0 = *(const ulonglong2*)(base + g * 4);
            ulonglong2 A1 = *(const ulonglong2*)(base + 64 + g * 4);
#pragma unroll
            for (int j = 0; j < 2; j++) {
                unsigned long long hp = pack2_dup(hreg[j][kk]);
                acc[j][0] = fma2(hp, A0.x, acc[j][0]);
                acc[j][1] = fma2(hp, A0.y, acc[j][1]);
                acc[j][2] = fma2(hp, A1.x, acc[j][2]);
                acc[j][3] = fma2(hp, A1.y, acc[j][3]);
            }
        }
    }

#pragma unroll
    for (int j = 0; j < 2; j++) {
        float* dst = g_HA + (size_t)(gbase + grow + j) * DX + g * 8;
        float2 v0 = unpack2(acc[j][0]), v1 = unpack2(acc[j][1]);
        float2 v2 = unpack2(acc[j][2]), v3 = unpack2(acc[j][3]);
        *(float4*)(dst)     = make_float4(v0.x, v0.y, v1.x, v1.y);
        *(float4*)(dst + 4) = make_float4(v2.x, v2.y, v3.x, v3.y);
    }
}

// ============================================================================
// Kernel 2: persistent segment-softmax attention, shortened critical path.
// 444 CTAs x 512 threads, 3 CTAs/SM. Per iteration (2 CTA barriers only):
//   mbar_wait -> LDS drain -> dots -> 5-step shfl butterfly -> exp -> STS z
//   -> SYNC (merged: buffer drained + z visible) -> warp15 issues refill
//   -> weighted sum -> STS red -> SYNC -> 128-thread epilogue (4/col + shfl).
// One bulk copy always in flight per CTA.
// ============================================================================
__global__ void __launch_bounds__(512, 3) attn_kernel(const float* __restrict__ x,
                                                      float* __restrict__ out) {
    extern __shared__ char smem[];
    const int t = threadIdx.x;
    const int w = t >> 5, l = t & 31;
    const int bid = blockIdx.x;

    // graphs [start, start+cnt): first 200 CTAs take 19, rest 18 (200*19+244*18=8192)
    const int start = bid * 18 + (bid < 200 ? bid : 200);
    const int cnt   = 18 + (bid < 200 ? 1 : 0);

    const uint32_t sb  = smem_u32(smem);
    const uint32_t mb0 = sb + MBAR_OFF;
    const uint32_t mb1 = sb + MBAR_OFF + 8;
    float4* red = (float4*)(smem + RED_OFF);    // [16 rows][stride 34 float4]
    float*  zwv = (float*)(smem + ZWV_OFF);     // 16 floats

    if (t == 0) {
        mbar_init(mb0, 1);
        mbar_init(mb1, 1);
        asm volatile("fence.proxy.async.shared::cta;" ::: "memory");
    }
    __syncthreads();

    // prologue: fill both buffers (x loads independent of ha_kernel)
    if (t == 0) {
        bulk_load(sb + BUF0_OFF, (const char*)x + (size_t)start * GRAPH_BYTES,
                  GRAPH_BYTES, mb0);
        if (cnt > 1)
            bulk_load(sb + BUF1_OFF, (const char*)x + (size_t)(start + 1) * GRAPH_BYTES,
                      GRAPH_BYTES, mb1);
    }

    // PDL: g_HA must be ready before the first read below
    asm volatile("griddepcontrol.wait;" ::: "memory");

    for (int i = 0; i < cnt; i++) {
        const int g = start + i;
        const int p = i & 1;

        // prefetch per-graph query before the barrier wait (hides LDG latency)
        const float4 hav = __ldg((const float4*)g_HA + g * (DX / 4) + l);

        mbar_wait(p ? mb1 : mb0, (i >> 1) & 1);

        // drain buffer into registers (conflict-free LDS.128)
        const float4* bp = (const float4*)(smem + (p ? BUF1_OFF : BUF0_OFF));
        float4 xv[4];
#pragma unroll
        for (int k = 0; k < 4; k++) xv[k] = bp[t + 512 * k];

        // logits: per-node dot partials -> warp butterfly (4 independent chains)
        float att[4];
        float zsum = 0.0f;
#pragma unroll
        for (int k = 0; k < 4; k++) {
            float e = xv[k].x * hav.x + xv[k].y * hav.y + xv[k].z * hav.z + xv[k].w * hav.w;
#pragma unroll
            for (int o = 16; o; o >>= 1) e += __shfl_xor_sync(0xffffffffu, e, o);
            float ex = __expf(e);      // unstabilized, faithful to reference
            att[k] = ex;
            zsum  += ex;
        }
        if (l == 0) zwv[w] = zsum;     // lane-uniform after butterfly

        __syncthreads();   // MERGED: buffer p fully drained AND zwv visible

        // refill buffer p with graph i+2 from warp 15 (warp 0 runs the epilogue)
        if (t == 480 && i + 2 < cnt)
            bulk_load(sb + (p ? BUF1_OFF : BUF0_OFF),
                      (const char*)x + (size_t)(g + 2) * GRAPH_BYTES,
                      GRAPH_BYTES, p ? mb1 : mb0);

        float z = 0.0f;
#pragma unroll
        for (int j = 0; j < 16; j++) z += zwv[j];   // broadcast LDS
        float inv = 1.0f / z;

        float4 o4 = make_float4(0.f, 0.f, 0.f, 0.f);
#pragma unroll
        for (int k = 0; k < 4; k++) {
            float aw = att[k] * inv;
            o4.x += aw * xv[k].x;
            o4.y += aw * xv[k].y;
            o4.z += aw * xv[k].z;
            o4.w += aw * xv[k].w;
        }
        red[w * 34 + l] = o4;
        __syncthreads();   // red visible (also orders iter-i zwv reads vs iter-i+1 writes)

        // epilogue: 128 threads, 4 per output column, then 2-step shfl combine
        if (t < 128) {
            const int sub = t & 3, col = t >> 2;   // col 0..31
            float4 s = red[sub * 34 + col];
#pragma unroll
            for (int jj = 1; jj < 4; jj++) {
                float4 r = red[(sub + jj * 4) * 34 + col];
                s.x += r.x; s.y += r.y; s.z += r.z; s.w += r.w;
            }
#pragma unroll
            for (int d = 1; d < 4; d <<= 1) {
                s.x += __shfl_xor_sync(0xffffffffu, s.x, d);
                s.y += __shfl_xor_sync(0xffffffffu, s.y, d);
                s.z += __shfl_xor_sync(0xffffffffu, s.z, d);
                s.w += __shfl_xor_sync(0xffffffffu, s.w, d);
            }
            if (sub == 0)
                ((float4*)out)[g * (DX / 4) + col] = s;
        }
        // next iteration's merged barrier orders red reuse after these reads
    }
}

// ============================================================================
// inputs (metadata order): h (8192x128 f32), x (524288x128 f32),
//                          a (128x128 f32), batch_num_nodes (8192 i32, all 64)
// output: out (8192x128 f32)
// ============================================================================
extern "C" void kernel_launch(void* const* d_in, const int* in_sizes, int n_in,
                              void* d_out, int out_size) {
    const float* h = (const float*)d_in[0];
    const float* x = (const float*)d_in[1];
    const float* a = (const float*)d_in[2];
    float* out = (float*)d_out;
    (void)in_sizes; (void)n_in; (void)out_size;

    cudaFuncSetAttribute(attn_kernel, cudaFuncAttributeMaxDynamicSharedMemorySize,
                         SMEM_BYTES);

    ha_kernel<<<MGRAPHS / 64, 512>>>(h, a);

    // attn with programmatic dependent launch (overlaps x loads with ha)
    cudaLaunchConfig_t cfg = {};
    cfg.gridDim  = dim3(ATTN_CTAS, 1, 1);
    cfg.blockDim = dim3(512, 1, 1);
    cfg.dynamicSmemBytes = SMEM_BYTES;
    cfg.stream = 0;
    cudaLaunchAttribute attr[1];
    attr[0].id = cudaLaunchAttributeProgrammaticStreamSerialization;
    attr[0].val.programmaticStreamSerializationAllowed = 1;
    cfg.attrs = attr;
    cfg.numAttrs = 1;
    cudaError_t e = cudaLaunchKernelEx(&cfg, attn_kernel, x, out);
    if (e != cudaSuccess || cudaGetLastError() != cudaSuccess) {
        attn_kernel<<<ATTN_CTAS, 512, SMEM_BYTES>>>(x, out);  // serialized fallback
    }
}